// round 4
// baseline (speedup 1.0000x reference)
#include <cuda_runtime.h>
#include <math.h>

// Problem constants (from reference setup_inputs): T=1024, B=64, V=256, L=256
#define CT_T 1024
#define CT_B 64
#define CT_V 256
#define CT_L 256
#define CT_S (2 * CT_L + 1)   // 513
#define FWD_THREADS 544       // 17 warps; threads 513..543 idle-but-barriering
#define NWARP (FWD_THREADS / 32)
#define RENORM_MASK 15        // renorm pipeline phases on t & 15

// Scratch (no cudaMalloc allowed)
__device__ float g_lse[CT_T * CT_B];
__device__ float g_per_loss[CT_B];

// ---------------------------------------------------------------------------
// Kernel 1: lse[t,b] = logsumexp over V of logits[t,b,:]
// One warp per (t,b) row (256 floats = 8 per lane, 2x float4).
// ---------------------------------------------------------------------------
__global__ void lse_kernel(const float* __restrict__ logits) {
    int warp = (blockIdx.x * blockDim.x + threadIdx.x) >> 5;
    int lane = threadIdx.x & 31;
    if (warp >= CT_T * CT_B) return;

    const float4* p = reinterpret_cast<const float4*>(logits + (size_t)warp * CT_V);
    float4 v0 = p[lane * 2 + 0];
    float4 v1 = p[lane * 2 + 1];

    float m = fmaxf(fmaxf(fmaxf(v0.x, v0.y), fmaxf(v0.z, v0.w)),
                    fmaxf(fmaxf(v1.x, v1.y), fmaxf(v1.z, v1.w)));
    #pragma unroll
    for (int o = 16; o > 0; o >>= 1)
        m = fmaxf(m, __shfl_xor_sync(0xFFFFFFFFu, m, o));

    float s = __expf(v0.x - m) + __expf(v0.y - m) + __expf(v0.z - m) + __expf(v0.w - m)
            + __expf(v1.x - m) + __expf(v1.y - m) + __expf(v1.z - m) + __expf(v1.w - m);
    #pragma unroll
    for (int o = 16; o > 0; o >>= 1)
        s += __shfl_xor_sync(0xFFFFFFFFu, s, o);

    if (lane == 0) g_lse[warp] = m + __logf(s);
}

// ---------------------------------------------------------------------------
// Kernel 2: CTC forward recursion in PROBABILITY domain, fp64 alpha.
// One block per batch element b. alpha[s] >= 0; per-step multiply by the
// softmax prob q[ext[s]] = exp(logit - lse) (computed fp32, stored fp64).
// fp64 gives ~708 nats of dynamic range below the renormalized max, covering
// the cross-s alpha spread that broke fp32 (87 nats).
// Pipelined renormalization every 16 steps (phases on t & 15):
//   phase 0: warp-max of fresh alpha -> wmax[wid]  (before barrier)
//   phase 1: warp 0 reduces wmax -> sh_inv, sh_m
//   phase 2: all threads multiply by sh_inv; tid0 does C += log(sh_m)
// Scale application and accounting happen in the SAME step, so state is
// consistent at any loop exit point.
// ---------------------------------------------------------------------------
__global__ __launch_bounds__(FWD_THREADS, 1)
void ctc_forward_kernel(const int* __restrict__ labels,
                        const float* __restrict__ logits,
                        const int* __restrict__ label_length,
                        const int* __restrict__ logit_length) {
    const int b    = blockIdx.x;
    const int tid  = threadIdx.x;
    const int wid  = tid >> 5;
    const int lane = tid & 31;
    const bool active = (tid < CT_S);

    __shared__ double qbuf[2][CT_V];       // softmax probs (fp64), double buffered
    __shared__ double A[2][CT_S + 2];      // alpha, 2-slot zero pad on the left
    __shared__ float  lse_s[CT_T];
    __shared__ double wmax[NWARP];
    __shared__ double sh_inv;
    __shared__ double sh_m;
    __shared__ double sh_C;

    // Stage per-b lse column
    for (int t = tid; t < CT_T; t += FWD_THREADS) lse_s[t] = g_lse[t * CT_B + b];

    // Per-thread extended-label state (constant across time)
    int    lbl   = 0;      // vocab index for q gather (0 = blank)
    double skipd = 0.0;    // 1.0 if s-2 -> s transition allowed
    if (active && (tid & 1)) {
        lbl = labels[b * CT_L + (tid >> 1)];
        int e2 = (tid >= 3) ? labels[b * CT_L + (tid >> 1) - 1] : -1;
        skipd = (lbl != 0 && lbl != e2) ? 1.0 : 0.0;
    }

    // Zero both alpha buffers (pads at [0],[1] stay zero forever)
    for (int i = tid; i < CT_S + 2; i += FWD_THREADS) {
        A[0][i] = 0.0;
        A[1][i] = 0.0;
    }
    if (tid < NWARP) wmax[tid] = 0.0;
    if (tid == 0) { sh_inv = 1.0; sh_m = 1.0; sh_C = 0.0; }

    const int Tb = min(max(logit_length[b], 0), CT_T);

    // Fill q for t=0 and t=1
    if (tid < CT_V / 4) {
        float4 x = reinterpret_cast<const float4*>(logits + ((size_t)0 * CT_B + b) * CT_V)[tid];
        float l = lse_s[0];
        double2* q0 = reinterpret_cast<double2*>(qbuf[0]);
        q0[tid * 2 + 0] = make_double2((double)__expf(x.x - l), (double)__expf(x.y - l));
        q0[tid * 2 + 1] = make_double2((double)__expf(x.z - l), (double)__expf(x.w - l));
        if (1 < Tb) {
            float4 x1 = reinterpret_cast<const float4*>(logits + ((size_t)1 * CT_B + b) * CT_V)[tid];
            float l1 = lse_s[1];
            double2* q1 = reinterpret_cast<double2*>(qbuf[1]);
            q1[tid * 2 + 0] = make_double2((double)__expf(x1.x - l1), (double)__expf(x1.y - l1));
            q1[tid * 2 + 1] = make_double2((double)__expf(x1.z - l1), (double)__expf(x1.w - l1));
        }
    }
    __syncthreads();

    // alpha at t=0: only s=0 (blank) and s=1 (first label)
    double a_own = 0.0;
    if (tid == 0) a_own = qbuf[0][0];
    else if (tid == 1) a_own = qbuf[0][lbl];
    if (active) A[0][2 + tid] = a_own;
    __syncthreads();

    int cur = 0;
    for (int t = 1; t < Tb; ++t) {
        const double* qc   = qbuf[t & 1];
        const double* Aold = A[cur] + 2;
        double*       Anew = A[cur ^ 1] + 2;
        const int phase = t & RENORM_MASK;

        // Prefetch logits row t+1 (exp'd after compute, stored to other buffer)
        float4 x;
        const bool pf = (tid < CT_V / 4) && (t + 1 < Tb);
        if (pf)
            x = reinterpret_cast<const float4*>(
                    logits + ((size_t)(t + 1) * CT_B + b) * CT_V)[tid];

        // Phase 1: one warp reduces per-warp maxima written at phase 0
        if (phase == 1 && tid < 32) {
            double m = (tid < NWARP) ? wmax[tid] : 0.0;
            #pragma unroll
            for (int o = 16; o > 0; o >>= 1)
                m = fmax(m, __shfl_xor_sync(0xFFFFFFFFu, m, o));
            if (tid == 0) {
                if (m > 0.0) { sh_inv = 1.0 / m; sh_m = m; }
                else         { sh_inv = 1.0;     sh_m = 1.0; }
            }
        }

        // Main update
        double anew = 0.0;
        if (active) {
            double a1 = Aold[tid - 1];
            double a2 = Aold[tid - 2];
            double sum = fma(skipd, a2, a_own + a1);
            anew = sum * qc[lbl];
            if (phase == 2) anew *= sh_inv;
            Anew[tid] = anew;
        }
        a_own = anew;

        // Phase 2 accounting: same step as scale application -> always consistent
        if (phase == 2 && tid == 0) sh_C += log(sh_m);

        // Phase 0: per-warp max of freshly computed alpha
        if (phase == 0) {
            double m = a_own;
            #pragma unroll
            for (int o = 16; o > 0; o >>= 1)
                m = fmax(m, __shfl_xor_sync(0xFFFFFFFFu, m, o));
            if (lane == 0) wmax[wid] = m;
        }

        // Store prefetched probs for t+1
        if (pf) {
            float l = lse_s[t + 1];
            double2* qn = reinterpret_cast<double2*>(qbuf[(t + 1) & 1]);
            qn[tid * 2 + 0] = make_double2((double)__expf(x.x - l), (double)__expf(x.y - l));
            qn[tid * 2 + 1] = make_double2((double)__expf(x.z - l), (double)__expf(x.w - l));
        }

        cur ^= 1;
        __syncthreads();
    }

    if (tid == 0) {
        int end = 2 * min(max(label_length[b], 0), CT_L);
        if (end > CT_S - 1) end = CT_S - 1;
        const double* Af = A[cur] + 2;
        double v;
        if (end == 0) v = 2.0 * Af[0];   // logaddexp(a[0], a[0])
        else          v = Af[end] + Af[end - 1];
        v = fmax(v, 1e-300);
        double ll = log(v) + sh_C;
        g_per_loss[b] = (float)(-ll);
    }
}

// ---------------------------------------------------------------------------
// Kernel 3: mean over B into d_out[0]
// ---------------------------------------------------------------------------
__global__ void mean_kernel(float* __restrict__ out) {
    __shared__ float sh[2];
    int tid = threadIdx.x;        // 64 threads
    float v = g_per_loss[tid];
    #pragma unroll
    for (int o = 16; o > 0; o >>= 1)
        v += __shfl_xor_sync(0xFFFFFFFFu, v, o);
    if ((tid & 31) == 0) sh[tid >> 5] = v;
    __syncthreads();
    if (tid == 0) out[0] = (sh[0] + sh[1]) * (1.0f / CT_B);
}

// ---------------------------------------------------------------------------
extern "C" void kernel_launch(void* const* d_in, const int* in_sizes, int n_in,
                              void* d_out, int out_size) {
    const int*   labels       = (const int*)d_in[0];   // [B, L]
    const float* logits       = (const float*)d_in[1]; // [T, B, V]
    const int*   label_length = (const int*)d_in[2];   // [B]
    const int*   logit_length = (const int*)d_in[3];   // [B]
    float*       out          = (float*)d_out;

    {
        int rows = CT_T * CT_B;
        int threads = 256;
        int blocks = (rows * 32 + threads - 1) / threads;
        lse_kernel<<<blocks, threads>>>(logits);
    }
    ctc_forward_kernel<<<CT_B, FWD_THREADS>>>(labels, logits, label_length, logit_length);
    mean_kernel<<<1, CT_B>>>(out);
}

// round 5
// speedup vs baseline: 4.2849x; 4.2849x over previous
#include <cuda_runtime.h>
#include <math.h>

// Problem constants (from reference setup_inputs): T=1024, B=64, V=256, L=256
#define CT_T 1024
#define CT_B 64
#define CT_V 256
#define CT_L 256
#define CT_S (2 * CT_L + 1)   // 513
#define FWD_THREADS 544       // 17 warps; threads 513..543 idle-but-barriering
#define PAD_E (-(1 << 28))    // exponent for pad slots: never dominates max

// Scratch (no cudaMalloc allowed)
__device__ float g_lse[CT_T * CT_B];
__device__ float g_per_loss[CT_B];

// ---------------------------------------------------------------------------
// Kernel 1: lse[t,b] = logsumexp over V of logits[t,b,:]
// One warp per (t,b) row (256 floats = 8 per lane, 2x float4).
// ---------------------------------------------------------------------------
__global__ void lse_kernel(const float* __restrict__ logits) {
    int warp = (blockIdx.x * blockDim.x + threadIdx.x) >> 5;
    int lane = threadIdx.x & 31;
    if (warp >= CT_T * CT_B) return;

    const float4* p = reinterpret_cast<const float4*>(logits + (size_t)warp * CT_V);
    float4 v0 = p[lane * 2 + 0];
    float4 v1 = p[lane * 2 + 1];

    float m = fmaxf(fmaxf(fmaxf(v0.x, v0.y), fmaxf(v0.z, v0.w)),
                    fmaxf(fmaxf(v1.x, v1.y), fmaxf(v1.z, v1.w)));
    #pragma unroll
    for (int o = 16; o > 0; o >>= 1)
        m = fmaxf(m, __shfl_xor_sync(0xFFFFFFFFu, m, o));

    float s = __expf(v0.x - m) + __expf(v0.y - m) + __expf(v0.z - m) + __expf(v0.w - m)
            + __expf(v1.x - m) + __expf(v1.y - m) + __expf(v1.z - m) + __expf(v1.w - m);
    #pragma unroll
    for (int o = 16; o > 0; o >>= 1)
        s += __shfl_xor_sync(0xFFFFFFFFu, s, o);

    if (lane == 0) g_lse[warp] = m + __logf(s);
}

// Exact power-of-two scale 2^(64*d) for d <= 0 (d <= -2 -> 0).
// Clamp BEFORE the shift so huge-negative pad exponents can't overflow.
__device__ __forceinline__ float scale64(int d) {
    d = max(d, -2);
    int bits = (127 + (d << 6)) << 23;   // d=0 -> 1.0f, d=-1 -> 2^-64
    bits = max(bits, 0);                 // d=-2 -> 0.0f
    return __int_as_float(bits);
}

// ---------------------------------------------------------------------------
// Kernel 2: CTC forward recursion in PROBABILITY domain with per-element
// software exponent: alpha[s] = v * 2^(64*e), v fp32, e int32 (packed float2).
// One block per batch element. Per-step, per-element cost is pure ALU/FMA —
// no MUFU, no DP, no block-wide renormalization.
// ---------------------------------------------------------------------------
__global__ __launch_bounds__(FWD_THREADS, 1)
void ctc_forward_kernel(const int* __restrict__ labels,
                        const float* __restrict__ logits,
                        const int* __restrict__ label_length,
                        const int* __restrict__ logit_length) {
    const int b   = blockIdx.x;
    const int tid = threadIdx.x;
    const bool active = (tid < CT_S);

    __shared__ float  qbuf[2][CT_V];      // softmax probs, double buffered
    __shared__ float2 A[2][CT_S + 2];     // {v, e-as-float-bits}, 2-slot left pad
    __shared__ float  lse_s[CT_T];

    // Stage per-b lse column
    for (int t = tid; t < CT_T; t += FWD_THREADS) lse_s[t] = g_lse[t * CT_B + b];

    // Per-thread extended-label state (constant across time)
    int   lbl   = 0;      // vocab index for q gather (0 = blank)
    float skipf = 0.0f;   // 1.0 if s-2 -> s transition allowed
    if (active && (tid & 1)) {
        lbl = labels[b * CT_L + (tid >> 1)];
        int e2 = (tid >= 3) ? labels[b * CT_L + (tid >> 1) - 1] : -1;
        skipf = (lbl != 0 && lbl != e2) ? 1.0f : 0.0f;
    }

    // Init: interior {0, e=0}; pads {0, e=PAD_E} so pads never dominate max-e
    for (int i = tid; i < CT_S + 2; i += FWD_THREADS) {
        int pe = (i < 2) ? PAD_E : 0;
        A[0][i] = make_float2(0.0f, __int_as_float(pe));
        A[1][i] = make_float2(0.0f, __int_as_float(pe));
    }

    const int Tb = min(max(logit_length[b], 0), CT_T);

    // Fill q for t=0 and t=1
    if (tid < CT_V / 4) {
        float4 x = reinterpret_cast<const float4*>(logits + ((size_t)0 * CT_B + b) * CT_V)[tid];
        float l = lse_s[0];
        float4 q;
        q.x = __expf(x.x - l); q.y = __expf(x.y - l);
        q.z = __expf(x.z - l); q.w = __expf(x.w - l);
        reinterpret_cast<float4*>(qbuf[0])[tid] = q;
        if (1 < Tb) {
            float4 x1 = reinterpret_cast<const float4*>(logits + ((size_t)1 * CT_B + b) * CT_V)[tid];
            float l1 = lse_s[1];
            float4 q1;
            q1.x = __expf(x1.x - l1); q1.y = __expf(x1.y - l1);
            q1.z = __expf(x1.z - l1); q1.w = __expf(x1.w - l1);
            reinterpret_cast<float4*>(qbuf[1])[tid] = q1;
        }
    }
    __syncthreads();

    // alpha at t=0: only s=0 (blank) and s=1 (first label)
    float a_v = 0.0f;
    int   a_e = 0;
    if (tid == 0) a_v = qbuf[0][0];
    else if (tid == 1) a_v = qbuf[0][lbl];
    if (active) A[0][2 + tid] = make_float2(a_v, __int_as_float(a_e));
    __syncthreads();

    int cur = 0;
    for (int t = 1; t < Tb; ++t) {
        const float*  qc   = qbuf[t & 1];
        const float2* Aold = A[cur];          // index s+2
        float2*       Anew = A[cur ^ 1];

        // Prefetch logits row t+1 (exp'd after compute, stored to other buffer)
        float4 x;
        const bool pf = (tid < CT_V / 4) && (t + 1 < Tb);
        if (pf)
            x = reinterpret_cast<const float4*>(
                    logits + ((size_t)(t + 1) * CT_B + b) * CT_V)[tid];

        if (active) {
            float2 f1 = Aold[tid + 1];   // alpha[s-1]
            float2 f2 = Aold[tid + 0];   // alpha[s-2]
            int e1 = __float_as_int(f1.y);
            int e2 = __float_as_int(f2.y);
            int em = max(a_e, max(e1, e2));

            float s = a_v * scale64(a_e - em);
            s += f1.x * scale64(e1 - em);
            s = fmaf(skipf * f2.x, scale64(e2 - em), s);

            float vn = s * qc[lbl];
            int   en = em;
            // Local renorm: keep v in [2^-32, 2^32); zeros drift e downward,
            // which keeps dead states from ever inflating the neighborhood max.
            if (vn < 0x1p-32f)      { vn *= 0x1p64f;  en -= 1; }
            else if (vn >= 0x1p32f) { vn *= 0x1p-64f; en += 1; }

            Anew[2 + tid] = make_float2(vn, __int_as_float(en));
            a_v = vn;
            a_e = en;
        }

        // Store prefetched probs for t+1
        if (pf) {
            float l = lse_s[t + 1];
            float4 q;
            q.x = __expf(x.x - l); q.y = __expf(x.y - l);
            q.z = __expf(x.z - l); q.w = __expf(x.w - l);
            reinterpret_cast<float4*>(qbuf[(t + 1) & 1])[tid] = q;
        }

        cur ^= 1;
        __syncthreads();
    }

    if (tid == 0) {
        int end = 2 * min(max(label_length[b], 0), CT_L);
        if (end > CT_S - 1) end = CT_S - 1;
        float2 fa = A[cur][2 + end];
        float2 fb = A[cur][2 + max(end - 1, 0)];
        int ea = __float_as_int(fa.y);
        int eb = __float_as_int(fb.y);
        int em = max(ea, eb);
        double s = (double)fa.x * exp2((double)(64 * (ea - em)))
                 + (double)fb.x * exp2((double)(64 * (eb - em)));
        s = fmax(s, 1e-300);
        double ll = log(s) + (double)em * 64.0 * 0.69314718055994530942;
        g_per_loss[b] = (float)(-ll);
    }
}

// ---------------------------------------------------------------------------
// Kernel 3: mean over B into d_out[0]
// ---------------------------------------------------------------------------
__global__ void mean_kernel(float* __restrict__ out) {
    __shared__ float sh[2];
    int tid = threadIdx.x;        // 64 threads
    float v = g_per_loss[tid];
    #pragma unroll
    for (int o = 16; o > 0; o >>= 1)
        v += __shfl_xor_sync(0xFFFFFFFFu, v, o);
    if ((tid & 31) == 0) sh[tid >> 5] = v;
    __syncthreads();
    if (tid == 0) out[0] = (sh[0] + sh[1]) * (1.0f / CT_B);
}

// ---------------------------------------------------------------------------
extern "C" void kernel_launch(void* const* d_in, const int* in_sizes, int n_in,
                              void* d_out, int out_size) {
    const int*   labels       = (const int*)d_in[0];   // [B, L]
    const float* logits       = (const float*)d_in[1]; // [T, B, V]
    const int*   label_length = (const int*)d_in[2];   // [B]
    const int*   logit_length = (const int*)d_in[3];   // [B]
    float*       out          = (float*)d_out;

    {
        int rows = CT_T * CT_B;
        int threads = 256;
        int blocks = (rows * 32 + threads - 1) / threads;
        lse_kernel<<<blocks, threads>>>(logits);
    }
    ctc_forward_kernel<<<CT_B, FWD_THREADS>>>(labels, logits, label_length, logit_length);
    mean_kernel<<<1, CT_B>>>(out);
}

// round 6
// speedup vs baseline: 5.5794x; 1.3021x over previous
#include <cuda_runtime.h>
#include <math.h>

// Problem constants (from reference setup_inputs): T=1024, B=64, V=256, L=256
#define CT_T 1024
#define CT_B 64
#define CT_V 256
#define CT_L 256
#define CT_S (2 * CT_L + 1)   // 513
#define PAD_E (-(1 << 28))    // exponent for pad/dead slots

// Forward kernel geometry
#define K_STEPS 16            // steps per barrier block
#define NW 6                  // warps
#define FWD_THREADS (NW * 32) // 192
#define A_OFF 32              // Abuf index = s + A_OFF (covers s >= -32)
#define A_SZ 640              // covers s in [-32, 608)

// Scratch (no cudaMalloc allowed)
__device__ float g_lse[CT_T * CT_B];
__device__ float g_per_loss[CT_B];

// ---------------------------------------------------------------------------
// Kernel 1: lse[t,b] = logsumexp over V of logits[t,b,:]
// ---------------------------------------------------------------------------
__global__ void lse_kernel(const float* __restrict__ logits) {
    int warp = (blockIdx.x * blockDim.x + threadIdx.x) >> 5;
    int lane = threadIdx.x & 31;
    if (warp >= CT_T * CT_B) return;

    const float4* p = reinterpret_cast<const float4*>(logits + (size_t)warp * CT_V);
    float4 v0 = p[lane * 2 + 0];
    float4 v1 = p[lane * 2 + 1];

    float m = fmaxf(fmaxf(fmaxf(v0.x, v0.y), fmaxf(v0.z, v0.w)),
                    fmaxf(fmaxf(v1.x, v1.y), fmaxf(v1.z, v1.w)));
    #pragma unroll
    for (int o = 16; o > 0; o >>= 1)
        m = fmaxf(m, __shfl_xor_sync(0xFFFFFFFFu, m, o));

    float s = __expf(v0.x - m) + __expf(v0.y - m) + __expf(v0.z - m) + __expf(v0.w - m)
            + __expf(v1.x - m) + __expf(v1.y - m) + __expf(v1.z - m) + __expf(v1.w - m);
    #pragma unroll
    for (int o = 16; o > 0; o >>= 1)
        s += __shfl_xor_sync(0xFFFFFFFFu, s, o);

    if (lane == 0) g_lse[warp] = m + __logf(s);
}

// Exact power-of-two scale 2^(64*d) for d <= 0 (d <= -2 -> 0).
// Clamp BEFORE the shift so huge-negative exponent gaps can't overflow.
__device__ __forceinline__ float scale64(int d) {
    d = max(d, -2);
    int bits = (127 + (d << 6)) << 23;   // d=0 -> 1.0f, d=-1 -> 2^-64
    bits = max(bits, 0);                 // d=-2 -> 0.0f
    return __int_as_float(bits);
}

// 2-term update (blank states: no skip transition)
__device__ __forceinline__ void upd2(float v0, int e0, float v1, int e1,
                                     float q, float& vn, int& en) {
    int em = max(e0, e1);
    float s = v0 * scale64(e0 - em) + v1 * scale64(e1 - em);
    float v = s * q;
    int e = em;
    if (v < 0x1p-32f)      { v *= 0x1p64f;  e -= 1; }
    else if (v >= 0x1p32f) { v *= 0x1p-64f; e += 1; }
    vn = v; en = e;
}

// 3-term update (label states: optional skip from s-2)
__device__ __forceinline__ void upd3(float v0, int e0, float v1, int e1,
                                     float v2, int e2, bool skip,
                                     float q, float& vn, int& en) {
    float v2x = skip ? v2 : 0.0f;
    int   e2x = skip ? e2 : PAD_E;
    int em = max(e0, max(e1, e2x));
    float s = v0 * scale64(e0 - em) + v1 * scale64(e1 - em);
    s = fmaf(v2x, scale64(e2x - em), s);
    float v = s * q;
    int e = em;
    if (v < 0x1p-32f)      { v *= 0x1p64f;  e -= 1; }
    else if (v >= 0x1p32f) { v *= 0x1p-64f; e += 1; }
    vn = v; en = e;
}

// One recursion step for this thread's 4 contiguous states.
// Layout: s = s_base + r; s_base = 96*warp - 32 + 4*lane (even).
// r=0,2 are blanks (q[0]); r=1,3 are labels (gather).
__device__ __forceinline__ void ctc_step(float va[4], int ea[4],
                                         const float* __restrict__ qrow,
                                         int lane, int lbl1, int lbl3,
                                         bool sk1, bool sk3) {
    float q0 = qrow[0];
    float q1 = qrow[lbl1];
    float q3 = qrow[lbl3];
    // Left neighbor thread's top state (old values)
    float lv = __shfl_up_sync(0xFFFFFFFFu, va[3], 1);
    int   le = __shfl_up_sync(0xFFFFFFFFu, ea[3], 1);
    if (lane == 0) { lv = 0.0f; le = PAD_E; }

    float nv0, nv1, nv2, nv3;
    int   ne0, ne1, ne2, ne3;
    upd2(va[0], ea[0], lv,    le,                      q0, nv0, ne0);
    upd3(va[1], ea[1], va[0], ea[0], lv,    le,  sk1, q1, nv1, ne1);
    upd2(va[2], ea[2], va[1], ea[1],                   q0, nv2, ne2);
    upd3(va[3], ea[3], va[2], ea[2], va[1], ea[1], sk3, q3, nv3, ne3);
    va[0] = nv0; ea[0] = ne0;
    va[1] = nv1; ea[1] = ne1;
    va[2] = nv2; ea[2] = ne2;
    va[3] = nv3; ea[3] = ne3;
}

// ---------------------------------------------------------------------------
// Kernel 2: CTC forward, warp-autonomous K-step blocks with redundant halo.
// Each warp covers 128 contiguous states (32 = recomputed left halo, 96 owned)
// in registers (4/thread). Within a 16-step block: no barriers, 2 shuffles +
// 3 SMEM reads per thread per step. One barrier + alpha/q SMEM exchange per
// block. alpha[s] = v * 2^(64*e) (fp32 v, int e) — unbounded dynamic range.
// ---------------------------------------------------------------------------
__global__ __launch_bounds__(FWD_THREADS, 1)
void ctc_forward_kernel(const int* __restrict__ labels,
                        const float* __restrict__ logits,
                        const int* __restrict__ label_length,
                        const int* __restrict__ logit_length) {
    const int b    = blockIdx.x;
    const int tid  = threadIdx.x;
    const int lane = tid & 31;
    const int warp = tid >> 5;
    const int s_base = 96 * warp - 32 + 4 * lane;   // even

    __shared__ float2 Abuf[2][A_SZ];
    __shared__ float  qblk[2][K_STEPS][CT_V];
    __shared__ float  lse_s[CT_T];

    // Stage per-b lse column
    for (int t = tid; t < CT_T; t += FWD_THREADS) lse_s[t] = g_lse[t * CT_B + b];
    // Init both alpha buffers to dead state
    for (int i = tid; i < A_SZ; i += FWD_THREADS) {
        float2 z = make_float2(0.0f, __int_as_float(PAD_E));
        Abuf[0][i] = z;
        Abuf[1][i] = z;
    }

    const int Tb = min(max(logit_length[b], 0), CT_T);

    // Per-thread label state (fixed across time). r=1,3 are label positions.
    int lbl1 = 0, lbl3 = 0;
    bool sk1 = false, sk3 = false;
    {
        int s1 = s_base + 1;
        if (s1 > 0 && s1 < CT_S) {
            lbl1 = labels[b * CT_L + (s1 >> 1)];
            if (s1 >= 3) {
                int pr = labels[b * CT_L + (s1 >> 1) - 1];
                sk1 = (lbl1 != 0) && (lbl1 != pr);
            }
        }
        int s3 = s_base + 3;
        if (s3 > 0 && s3 < CT_S) {
            lbl3 = labels[b * CT_L + (s3 >> 1)];
            if (s3 >= 3) {
                int pr = labels[b * CT_L + (s3 >> 1) - 1];
                sk3 = (lbl3 != 0) && (lbl3 != pr);
            }
        }
    }
    __syncthreads();

    // t=0 init: alpha[0] = q0(blank), alpha[1] = q0(first label); e = 0
    if (tid == 0) {
        float l0 = lse_s[0];
        float a0 = __expf(logits[(size_t)b * CT_V + 0] - l0);
        int   e1 = labels[b * CT_L + 0];
        float a1 = __expf(logits[(size_t)b * CT_V + e1] - l0);
        Abuf[0][A_OFF + 0] = make_float2(a0, __int_as_float(0));
        Abuf[0][A_OFF + 1] = make_float2(a1, __int_as_float(0));
    }
    // Fill q block 0: rows t = 1..16
    for (int i = tid; i < K_STEPS * (CT_V / 4); i += FWD_THREADS) {
        int row = i >> 6;          // CT_V/4 = 64 float4 per row
        int c4  = i & 63;
        int t   = 1 + row;
        float4 q = make_float4(0.f, 0.f, 0.f, 0.f);
        if (t < Tb) {
            float4 x = reinterpret_cast<const float4*>(
                           logits + ((size_t)t * CT_B + b) * CT_V)[c4];
            float l = lse_s[t];
            q.x = __expf(x.x - l); q.y = __expf(x.y - l);
            q.z = __expf(x.z - l); q.w = __expf(x.w - l);
        }
        reinterpret_cast<float4*>(qblk[0][row])[c4] = q;
    }
    __syncthreads();

    int p = 0;
    for (int t0 = 1; t0 < Tb; t0 += K_STEPS) {
        // Load this warp's 128-state window (halo + owned) into registers
        float va[4]; int ea[4];
        #pragma unroll
        for (int r = 0; r < 4; ++r) {
            float2 f = Abuf[p][A_OFF + s_base + r];
            va[r] = f.x;
            ea[r] = __float_as_int(f.y);
        }

        // Prefetch next block's logits rows (t0+16 .. t0+31) into registers
        float4 pref[6];
        bool   pv[6];
        #pragma unroll
        for (int it = 0; it < 6; ++it) {
            int i = tid + it * FWD_THREADS;
            int row = i >> 6, c4 = i & 63;
            int t = t0 + K_STEPS + row;
            pv[it] = (i < K_STEPS * 64) && (t < Tb);
            if (pv[it])
                pref[it] = __ldg(reinterpret_cast<const float4*>(
                               logits + ((size_t)t * CT_B + b) * CT_V) + c4);
        }

        const int jmax = min(K_STEPS, Tb - t0);
        const float (*qb)[CT_V] = qblk[p];
        if (jmax == K_STEPS) {
            #pragma unroll 4
            for (int j = 0; j < K_STEPS; ++j)
                ctc_step(va, ea, qb[j], lane, lbl1, lbl3, sk1, sk3);
        } else {
            for (int j = 0; j < jmax; ++j)
                ctc_step(va, ea, qb[j], lane, lbl1, lbl3, sk1, sk3);
        }

        // Exp + store prefetched rows into the other q buffer
        #pragma unroll
        for (int it = 0; it < 6; ++it) {
            if (pv[it]) {
                int i = tid + it * FWD_THREADS;
                int row = i >> 6, c4 = i & 63;
                float l = lse_s[t0 + K_STEPS + row];
                float4 x = pref[it];
                float4 q;
                q.x = __expf(x.x - l); q.y = __expf(x.y - l);
                q.z = __expf(x.z - l); q.w = __expf(x.w - l);
                reinterpret_cast<float4*>(qblk[p ^ 1][row])[c4] = q;
            }
        }

        // Store owned states (local index >= 32 <=> lane >= 8)
        if (lane >= 8) {
            #pragma unroll
            for (int r = 0; r < 4; ++r)
                Abuf[p ^ 1][A_OFF + s_base + r] =
                    make_float2(va[r], __int_as_float(ea[r]));
        }
        __syncthreads();
        p ^= 1;
    }

    if (tid == 0) {
        int end = 2 * min(max(label_length[b], 0), CT_L);
        if (end > CT_S - 1) end = CT_S - 1;
        float2 fa = Abuf[p][A_OFF + end];
        float2 fb = Abuf[p][A_OFF + max(end - 1, 0)];
        int ea_ = __float_as_int(fa.y);
        int eb_ = __float_as_int(fb.y);
        int em  = max(ea_, eb_);
        double s = (double)fa.x * exp2((double)(64 * (ea_ - em)))
                 + (double)fb.x * exp2((double)(64 * (eb_ - em)));
        if (end == 0) s = 2.0 * (double)fa.x;  // logaddexp(a[0], a[0])
        s = fmax(s, 1e-300);
        double ll = log(s) + (double)em * 64.0 * 0.69314718055994530942;
        g_per_loss[b] = (float)(-ll);
    }
}

// ---------------------------------------------------------------------------
// Kernel 3: mean over B into d_out[0]
// ---------------------------------------------------------------------------
__global__ void mean_kernel(float* __restrict__ out) {
    __shared__ float sh[2];
    int tid = threadIdx.x;        // 64 threads
    float v = g_per_loss[tid];
    #pragma unroll
    for (int o = 16; o > 0; o >>= 1)
        v += __shfl_xor_sync(0xFFFFFFFFu, v, o);
    if ((tid & 31) == 0) sh[tid >> 5] = v;
    __syncthreads();
    if (tid == 0) out[0] = (sh[0] + sh[1]) * (1.0f / CT_B);
}

// ---------------------------------------------------------------------------
extern "C" void kernel_launch(void* const* d_in, const int* in_sizes, int n_in,
                              void* d_out, int out_size) {
    const int*   labels       = (const int*)d_in[0];   // [B, L]
    const float* logits       = (const float*)d_in[1]; // [T, B, V]
    const int*   label_length = (const int*)d_in[2];   // [B]
    const int*   logit_length = (const int*)d_in[3];   // [B]
    float*       out          = (float*)d_out;

    {
        int rows = CT_T * CT_B;
        int threads = 256;
        int blocks = (rows * 32 + threads - 1) / threads;
        lse_kernel<<<blocks, threads>>>(logits);
    }
    ctc_forward_kernel<<<CT_B, FWD_THREADS>>>(labels, logits, label_length, logit_length);
    mean_kernel<<<1, CT_B>>>(out);
}

// round 7
// speedup vs baseline: 9.0881x; 1.6289x over previous
#include <cuda_runtime.h>
#include <math.h>

// Problem constants (from reference setup_inputs): T=1024, B=64, V=256, L=256
#define CT_T 1024
#define CT_B 64
#define CT_V 256
#define CT_L 256
#define CT_S (2 * CT_L + 1)   // 513
#define PAD_E (-(1 << 28))    // exponent for pad/dead slots

// Forward kernel geometry
#define K_STEPS 16            // steps per barrier block (halo = 2*K = 32)
#define NW 6                  // warps
#define FWD_THREADS (NW * 32) // 192
#define A_OFF 32              // Abuf index = s + A_OFF (covers s >= -32)
#define A_SZ 640              // covers s in [-32, 608)

// Scratch (no cudaMalloc allowed)
__device__ float g_lse[CT_T * CT_B];
__device__ float g_per_loss[CT_B];

// ---------------------------------------------------------------------------
// Kernel 1: lse[t,b] = logsumexp over V of logits[t,b,:]
// ---------------------------------------------------------------------------
__global__ void lse_kernel(const float* __restrict__ logits) {
    int warp = (blockIdx.x * blockDim.x + threadIdx.x) >> 5;
    int lane = threadIdx.x & 31;
    if (warp >= CT_T * CT_B) return;

    const float4* p = reinterpret_cast<const float4*>(logits + (size_t)warp * CT_V);
    float4 v0 = p[lane * 2 + 0];
    float4 v1 = p[lane * 2 + 1];

    float m = fmaxf(fmaxf(fmaxf(v0.x, v0.y), fmaxf(v0.z, v0.w)),
                    fmaxf(fmaxf(v1.x, v1.y), fmaxf(v1.z, v1.w)));
    #pragma unroll
    for (int o = 16; o > 0; o >>= 1)
        m = fmaxf(m, __shfl_xor_sync(0xFFFFFFFFu, m, o));

    float s = __expf(v0.x - m) + __expf(v0.y - m) + __expf(v0.z - m) + __expf(v0.w - m)
            + __expf(v1.x - m) + __expf(v1.y - m) + __expf(v1.z - m) + __expf(v1.w - m);
    #pragma unroll
    for (int o = 16; o > 0; o >>= 1)
        s += __shfl_xor_sync(0xFFFFFFFFu, s, o);

    if (lane == 0) g_lse[warp] = m + __logf(s);
}

// Exact power-of-two scale 2^(64*d) for d <= 0 (d <= -2 -> 0).
// Clamp BEFORE the shift so huge-negative exponent gaps can't overflow.
__device__ __forceinline__ float scale64(int d) {
    d = max(d, -2);
    int bits = (127 + (d << 6)) << 23;   // d=0 -> 1.0f, d=-1 -> 2^-64
    bits = max(bits, 0);                 // d=-2 -> 0.0f
    return __int_as_float(bits);
}

// One recursion step for this thread's 4 contiguous states, SHARED exponent e.
// Layout: s = s_base + r; s_base = 96*warp - 32 + 4*lane (even).
// r=0,2 are blanks (q[0]); r=1,3 are labels (gather).
// Only the shuffled-in left value needs exponent alignment; intra-thread adds
// are plain fp32. One predicated renorm per thread per step.
__device__ __forceinline__ void ctc_step(float va[4], int& e,
                                         const float* __restrict__ qrow,
                                         int lane, int lbl1, int lbl3,
                                         float sk1f, float sk3f) {
    float q0 = qrow[0];
    float q1 = qrow[lbl1];
    float q3 = qrow[lbl3];
    // Left neighbor thread's top state (old values)
    float lv = __shfl_up_sync(0xFFFFFFFFu, va[3], 1);
    int   le = __shfl_up_sync(0xFFFFFFFFu, e, 1);
    if (lane == 0) { lv = 0.0f; le = PAD_E; }

    int   em = max(e, le);
    float so = scale64(e - em);    // usually 1.0
    float sl = scale64(le - em);
    float lvs = lv * sl;
    float v0 = va[0] * so;
    float v1 = va[1] * so;
    float v2 = va[2] * so;
    float v3 = va[3] * so;

    float n0 = (v0 + lvs) * q0;
    float n1 = fmaf(sk1f, lvs, v1 + v0) * q1;
    float n2 = (v2 + v1) * q0;
    float n3 = fmaf(sk3f, v1, v3 + v2) * q3;

    // Per-thread renorm: keep max in [2^-32, 2^32)
    float m = fmaxf(fmaxf(n0, n1), fmaxf(n2, n3));
    float f = 1.0f;
    int  de = 0;
    if (m < 0x1p-32f)      { f = 0x1p64f;  de = -1; }
    else if (m >= 0x1p32f) { f = 0x1p-64f; de = 1;  }
    va[0] = n0 * f;
    va[1] = n1 * f;
    va[2] = n2 * f;
    va[3] = n3 * f;
    e = em + de;
}

// ---------------------------------------------------------------------------
// Kernel 2: CTC forward, warp-autonomous K-step blocks with redundant halo.
// Each warp covers 128 contiguous states (32 = recomputed left halo, 96 owned)
// in registers (4/thread) with ONE shared software exponent per thread:
// alpha[s] = v * 2^(64*e). Within a 16-step block: no barriers, 2 shuffles +
// 3 SMEM reads per thread per step, pure FADD/FFMA math. One barrier + SMEM
// exchange per block.
// ---------------------------------------------------------------------------
__global__ __launch_bounds__(FWD_THREADS, 1)
void ctc_forward_kernel(const int* __restrict__ labels,
                        const float* __restrict__ logits,
                        const int* __restrict__ label_length,
                        const int* __restrict__ logit_length) {
    const int b    = blockIdx.x;
    const int tid  = threadIdx.x;
    const int lane = tid & 31;
    const int warp = tid >> 5;
    const int s_base = 96 * warp - 32 + 4 * lane;   // even

    __shared__ float2 Abuf[2][A_SZ];
    __shared__ float  qblk[2][K_STEPS][CT_V];
    __shared__ float  lse_s[CT_T];

    // Stage per-b lse column
    for (int t = tid; t < CT_T; t += FWD_THREADS) lse_s[t] = g_lse[t * CT_B + b];
    // Init both alpha buffers to dead state
    for (int i = tid; i < A_SZ; i += FWD_THREADS) {
        float2 z = make_float2(0.0f, __int_as_float(PAD_E));
        Abuf[0][i] = z;
        Abuf[1][i] = z;
    }

    const int Tb = min(max(logit_length[b], 0), CT_T);

    // Per-thread label state (fixed across time). r=1,3 are label positions.
    int lbl1 = 0, lbl3 = 0;
    float sk1f = 0.0f, sk3f = 0.0f;
    {
        int s1 = s_base + 1;
        if (s1 > 0 && s1 < CT_S) {
            lbl1 = labels[b * CT_L + (s1 >> 1)];
            if (s1 >= 3) {
                int pr = labels[b * CT_L + (s1 >> 1) - 1];
                sk1f = ((lbl1 != 0) && (lbl1 != pr)) ? 1.0f : 0.0f;
            }
        }
        int s3 = s_base + 3;
        if (s3 > 0 && s3 < CT_S) {
            lbl3 = labels[b * CT_L + (s3 >> 1)];
            if (s3 >= 3) {
                int pr = labels[b * CT_L + (s3 >> 1) - 1];
                sk3f = ((lbl3 != 0) && (lbl3 != pr)) ? 1.0f : 0.0f;
            }
        }
    }
    __syncthreads();

    // t=0 init: alpha[0] = q0(blank), alpha[1] = q0(first label); e = 0
    if (tid == 0) {
        float l0 = lse_s[0];
        float a0 = __expf(logits[(size_t)b * CT_V + 0] - l0);
        int   e1 = labels[b * CT_L + 0];
        float a1 = __expf(logits[(size_t)b * CT_V + e1] - l0);
        Abuf[0][A_OFF + 0] = make_float2(a0, __int_as_float(0));
        Abuf[0][A_OFF + 1] = make_float2(a1, __int_as_float(0));
    }
    // Fill q block 0: rows t = 1..16
    for (int i = tid; i < K_STEPS * (CT_V / 4); i += FWD_THREADS) {
        int row = i >> 6;          // CT_V/4 = 64 float4 per row
        int c4  = i & 63;
        int t   = 1 + row;
        float4 q = make_float4(0.f, 0.f, 0.f, 0.f);
        if (t < Tb) {
            float4 x = reinterpret_cast<const float4*>(
                           logits + ((size_t)t * CT_B + b) * CT_V)[c4];
            float l = lse_s[t];
            q.x = __expf(x.x - l); q.y = __expf(x.y - l);
            q.z = __expf(x.z - l); q.w = __expf(x.w - l);
        }
        reinterpret_cast<float4*>(qblk[0][row])[c4] = q;
    }
    __syncthreads();

    int p = 0;
    for (int t0 = 1; t0 < Tb; t0 += K_STEPS) {
        // Load this warp's 128-state window (halo + owned) into registers,
        // aligning the 4 per-state exponents to one shared thread exponent.
        float va[4]; int e;
        {
            float2 f0 = Abuf[p][A_OFF + s_base + 0];
            float2 f1 = Abuf[p][A_OFF + s_base + 1];
            float2 f2 = Abuf[p][A_OFF + s_base + 2];
            float2 f3 = Abuf[p][A_OFF + s_base + 3];
            int e0 = __float_as_int(f0.y), e1 = __float_as_int(f1.y);
            int e2 = __float_as_int(f2.y), e3 = __float_as_int(f3.y);
            e = max(max(e0, e1), max(e2, e3));
            va[0] = f0.x * scale64(e0 - e);
            va[1] = f1.x * scale64(e1 - e);
            va[2] = f2.x * scale64(e2 - e);
            va[3] = f3.x * scale64(e3 - e);
        }

        // Prefetch next block's logits rows (t0+16 .. t0+31) into registers
        float4 pref[6];
        bool   pv[6];
        #pragma unroll
        for (int it = 0; it < 6; ++it) {
            int i = tid + it * FWD_THREADS;
            int row = i >> 6, c4 = i & 63;
            int t = t0 + K_STEPS + row;
            pv[it] = (i < K_STEPS * 64) && (t < Tb);
            if (pv[it])
                pref[it] = __ldg(reinterpret_cast<const float4*>(
                               logits + ((size_t)t * CT_B + b) * CT_V) + c4);
        }

        const int jmax = min(K_STEPS, Tb - t0);
        const float (*qb)[CT_V] = qblk[p];
        if (jmax == K_STEPS) {
            #pragma unroll 4
            for (int j = 0; j < K_STEPS; ++j)
                ctc_step(va, e, qb[j], lane, lbl1, lbl3, sk1f, sk3f);
        } else {
            for (int j = 0; j < jmax; ++j)
                ctc_step(va, e, qb[j], lane, lbl1, lbl3, sk1f, sk3f);
        }

        // Exp + store prefetched rows into the other q buffer
        #pragma unroll
        for (int it = 0; it < 6; ++it) {
            if (pv[it]) {
                int i = tid + it * FWD_THREADS;
                int row = i >> 6, c4 = i & 63;
                float l = lse_s[t0 + K_STEPS + row];
                float4 x = pref[it];
                float4 q;
                q.x = __expf(x.x - l); q.y = __expf(x.y - l);
                q.z = __expf(x.z - l); q.w = __expf(x.w - l);
                reinterpret_cast<float4*>(qblk[p ^ 1][row])[c4] = q;
            }
        }

        // Store owned states (local index >= 32 <=> lane >= 8)
        if (lane >= 8) {
            float eb = __int_as_float(e);
            #pragma unroll
            for (int r = 0; r < 4; ++r)
                Abuf[p ^ 1][A_OFF + s_base + r] = make_float2(va[r], eb);
        }
        __syncthreads();
        p ^= 1;
    }

    if (tid == 0) {
        int end = 2 * min(max(label_length[b], 0), CT_L);
        if (end > CT_S - 1) end = CT_S - 1;
        float2 fa = Abuf[p][A_OFF + end];
        float2 fb = Abuf[p][A_OFF + max(end - 1, 0)];
        int ea_ = __float_as_int(fa.y);
        int eb_ = __float_as_int(fb.y);
        int em  = max(ea_, eb_);
        double s = (double)fa.x * exp2((double)(64 * (ea_ - em)))
                 + (double)fb.x * exp2((double)(64 * (eb_ - em)));
        if (end == 0) s = 2.0 * (double)fa.x;  // logaddexp(a[0], a[0])
        s = fmax(s, 1e-300);
        double ll = log(s) + (double)em * 64.0 * 0.69314718055994530942;
        g_per_loss[b] = (float)(-ll);
    }
}

// ---------------------------------------------------------------------------
// Kernel 3: mean over B into d_out[0]
// ---------------------------------------------------------------------------
__global__ void mean_kernel(float* __restrict__ out) {
    __shared__ float sh[2];
    int tid = threadIdx.x;        // 64 threads
    float v = g_per_loss[tid];
    #pragma unroll
    for (int o = 16; o > 0; o >>= 1)
        v += __shfl_xor_sync(0xFFFFFFFFu, v, o);
    if ((tid & 31) == 0) sh[tid >> 5] = v;
    __syncthreads();
    if (tid == 0) out[0] = (sh[0] + sh[1]) * (1.0f / CT_B);
}

// ---------------------------------------------------------------------------
extern "C" void kernel_launch(void* const* d_in, const int* in_sizes, int n_in,
                              void* d_out, int out_size) {
    const int*   labels       = (const int*)d_in[0];   // [B, L]
    const float* logits       = (const float*)d_in[1]; // [T, B, V]
    const int*   label_length = (const int*)d_in[2];   // [B]
    const int*   logit_length = (const int*)d_in[3];   // [B]
    float*       out          = (float*)d_out;

    {
        int rows = CT_T * CT_B;
        int threads = 256;
        int blocks = (rows * 32 + threads - 1) / threads;
        lse_kernel<<<blocks, threads>>>(logits);
    }
    ctc_forward_kernel<<<CT_B, FWD_THREADS>>>(labels, logits, label_length, logit_length);
    mean_kernel<<<1, CT_B>>>(out);
}